// round 1
// baseline (speedup 1.0000x reference)
#include <cuda_runtime.h>

#define EPSV 1e-5f

// ---------------- shared memory layout (float offsets) ----------------
// region1 (7168): pooled[128][56]  -> later q/k/v/attn  -> later xpadA[32][9][12]
// region2 (3456): xbuf[32][56] (first 1792) -> later xpadB[32][9][12]
// ws      (5520): w_cr (32x129) + qw/kw (4x33 each) + vw (32x33)
//                 -> later w_res half (32x145) -> later w1 (16x289) + w2 (144)
// red     (64)  : LN reduction scratch
#define R1_OFF   0
#define R2_OFF   7168
#define WS_OFF   10624
#define RED_OFF  16144
#define SMEM_FLOATS 16208

#define Q_OFF    (R1_OFF + 0)      // 4*56
#define K_OFF    (R1_OFF + 224)    // 4*56
#define V_OFF    (R1_OFF + 448)    // 32*56
#define ATT_OFF  (R1_OFF + 2240)   // 56*57 = 3192 (padded rows, stride 57)

#define WCR_OFF  (WS_OFF + 0)      // 32*129
#define QW_OFF   (WS_OFF + 4160)   // 4*33
#define KW_OFF   (WS_OFF + 4292)   // 4*33
#define VW_OFF   (WS_OFF + 4424)   // 32*33  (ends at WS_OFF+5480)

// xpad layout: channel stride 108 (9 rows * 12 cols), row stride 12, interior at [1..7][1..8]

// acc[8] += w[c*wstride] * x8[c*ldx .. +7] for c in [0,K)
__device__ __forceinline__ void gemm_row8(float acc[8], const float* __restrict__ w,
                                          int wstride, const float* __restrict__ xcol,
                                          int ldx, int K) {
    for (int c = 0; c < K; ++c) {
        float wv = w[c * wstride];
        const float4* px = (const float4*)(xcol + c * ldx);
        float4 A = px[0], B = px[1];
        acc[0] = fmaf(wv, A.x, acc[0]); acc[1] = fmaf(wv, A.y, acc[1]);
        acc[2] = fmaf(wv, A.z, acc[2]); acc[3] = fmaf(wv, A.w, acc[3]);
        acc[4] = fmaf(wv, B.x, acc[4]); acc[5] = fmaf(wv, B.y, acc[5]);
        acc[6] = fmaf(wv, B.z, acc[6]); acc[7] = fmaf(wv, B.w, acc[7]);
    }
}

// 3x3 conv accumulate over nch input channels, one (o,p) output row (8 q-values).
// xpad: base of channel 0 for this conv's input (padded 9x12 per channel)
// wrow: smem weights for this o, stride 9 per input channel
__device__ __forceinline__ void conv3x3_row(float acc[8], const float* __restrict__ xpad,
                                            const float* __restrict__ wrow, int nch, int p) {
    for (int i = 0; i < nch; ++i) {
        const float4* X = (const float4*)(xpad + i * 108 + p * 12);
        float4 a0 = X[0], a1 = X[1], a2 = X[2];
        float4 b0 = X[3], b1 = X[4], b2 = X[5];
        float4 c0 = X[6], c1 = X[7], c2 = X[8];
        float x0[12] = {a0.x,a0.y,a0.z,a0.w,a1.x,a1.y,a1.z,a1.w,a2.x,a2.y,a2.z,a2.w};
        float x1[12] = {b0.x,b0.y,b0.z,b0.w,b1.x,b1.y,b1.z,b1.w,b2.x,b2.y,b2.z,b2.w};
        float x2[12] = {c0.x,c0.y,c0.z,c0.w,c1.x,c1.y,c1.z,c1.w,c2.x,c2.y,c2.z,c2.w};
        const float* w = wrow + i * 9;
        float w0=w[0],w1=w[1],w2=w[2],w3=w[3],w4=w[4],w5=w[5],w6=w[6],w7=w[7],w8=w[8];
        #pragma unroll
        for (int q = 0; q < 8; ++q) {
            float s = fmaf(w0, x0[q],   fmaf(w1, x0[q+1], fmaf(w2, x0[q+2],
                      fmaf(w3, x1[q],   fmaf(w4, x1[q+1], fmaf(w5, x1[q+2],
                      fmaf(w6, x2[q],   fmaf(w7, x2[q+1],      w8 * x2[q+2]))))))));
            acc[q] += s;
        }
    }
}

__global__ void __launch_bounds__(256) occ_fused_kernel(
    const float* __restrict__ mg,
    const float* __restrict__ w_cr, const float* __restrict__ b_cr,
    const float* __restrict__ bnr_w, const float* __restrict__ bnr_b,
    const float* __restrict__ bnr_m, const float* __restrict__ bnr_v,
    const float* __restrict__ q_w,  const float* __restrict__ q_b,
    const float* __restrict__ k_w,  const float* __restrict__ k_b,
    const float* __restrict__ v_w,  const float* __restrict__ v_b,
    const float* __restrict__ gamma,
    const float* __restrict__ ln_w, const float* __restrict__ ln_b,
    const float* __restrict__ w_res, const float* __restrict__ b_res,
    const float* __restrict__ bnres_w, const float* __restrict__ bnres_b,
    const float* __restrict__ bnres_m, const float* __restrict__ bnres_v,
    const float* __restrict__ w1,  const float* __restrict__ b1,
    const float* __restrict__ bn1_w, const float* __restrict__ bn1_b,
    const float* __restrict__ bn1_m, const float* __restrict__ bn1_v,
    const float* __restrict__ w2,  const float* __restrict__ b2,
    float* __restrict__ out)
{
    extern __shared__ float sm[];
    const int t = threadIdx.x;
    const int b = blockIdx.x;

    float* pooled = sm + R1_OFF;
    float* xbuf   = sm + R2_OFF;
    float* ws     = sm + WS_OFF;
    float* red    = sm + RED_OFF;

    // ============ Stage A: adaptive avg pool 16x16 -> 7x8, plus weight staging ============
    {
        const float* in = mg + (size_t)b * 32768;   // 128*16*16
        for (int idx = t; idx < 7168; idx += 256) {
            int c = idx / 56, s = idx - c * 56, p = s >> 3, q = s & 7;
            int r0 = (p * 16) / 7;
            int r1 = ((p + 1) * 16 + 6) / 7;
            const float2* bp = (const float2*)(in + c * 256 + q * 2);
            float acc = 0.f;
            for (int r = r0; r < r1; ++r) { float2 v2 = bp[r * 8]; acc += v2.x + v2.y; }
            pooled[idx] = acc * (0.5f / (float)(r1 - r0));
        }
        for (int idx = t; idx < 4096; idx += 256) {
            int o = idx >> 7, c = idx & 127;
            sm[WCR_OFF + o * 129 + c] = w_cr[idx];
        }
        for (int idx = t; idx < 128; idx += 256) {
            int d = idx >> 5, o = idx & 31;
            sm[QW_OFF + d * 33 + o] = q_w[idx];
            sm[KW_OFF + d * 33 + o] = k_w[idx];
        }
        for (int idx = t; idx < 1024; idx += 256) {
            int c = idx >> 5, o = idx & 31;
            sm[VW_OFF + c * 33 + o] = v_w[idx];
        }
    }
    __syncthreads();

    // ============ Stage B: 1x1 channel reduce 128->32 + BN + ReLU -> xbuf[32][56] ============
    if (t < 224) {
        int o = t / 7, p = t % 7;
        float acc[8] = {0,0,0,0,0,0,0,0};
        gemm_row8(acc, sm + WCR_OFF + o * 129, 1, pooled + p * 8, 56, 128);
        float sc = bnr_w[o] * rsqrtf(bnr_v[o] + EPSV);
        float bi = b_cr[o] * sc + bnr_b[o] - bnr_m[o] * sc;
        float* xo = xbuf + o * 56 + p * 8;
        #pragma unroll
        for (int q = 0; q < 8; ++q) xo[q] = fmaxf(fmaf(acc[q], sc, bi), 0.f);
    }
    __syncthreads();

    // ============ Stage C1: q,k,v projections ============
    for (int u = t; u < 280; u += 256) {
        if (u < 224) {
            int c = u / 7, p = u % 7;
            float bias = v_b[c];
            float acc[8] = {bias,bias,bias,bias,bias,bias,bias,bias};
            gemm_row8(acc, sm + VW_OFF + c * 33, 1, xbuf + p * 8, 56, 32);
            float* vo = sm + V_OFF + c * 56 + p * 8;
            #pragma unroll
            for (int q = 0; q < 8; ++q) vo[q] = acc[q];
        } else {
            int u2 = u - 224;
            int dk = u2 / 7, p = u2 % 7;
            int d = dk & 3;
            const float* wp = sm + (dk < 4 ? QW_OFF : KW_OFF) + d * 33;
            float bias = (dk < 4) ? q_b[d] : k_b[d];
            float acc[8] = {bias,bias,bias,bias,bias,bias,bias,bias};
            gemm_row8(acc, wp, 1, xbuf + p * 8, 56, 32);
            float* dst = sm + (dk < 4 ? Q_OFF : K_OFF) + d * 56 + p * 8;
            #pragma unroll
            for (int q = 0; q < 8; ++q) dst[q] = acc[q];
        }
    }
    __syncthreads();

    // ============ Stage C2: scores S[i][j] = sum_d q[d][i]*k[d][j] ============
    for (int u = t; u < 392; u += 256) {
        int i = u / 7, pj = u % 7;
        float acc[8] = {0,0,0,0,0,0,0,0};
        gemm_row8(acc, sm + Q_OFF + i, 56, sm + K_OFF + pj * 8, 56, 4);
        float* arow = sm + ATT_OFF + i * 57 + pj * 8;
        #pragma unroll
        for (int q = 0; q < 8; ++q) arow[q] = acc[q];
    }
    __syncthreads();

    // ============ softmax over j per row i ============
    if (t < 56) {
        float* row = sm + ATT_OFF + t * 57;
        float m = -1e30f;
        for (int j = 0; j < 56; ++j) m = fmaxf(m, row[j]);
        float ssum = 0.f;
        for (int j = 0; j < 56; ++j) { float e = __expf(row[j] - m); row[j] = e; ssum += e; }
        float inv = 1.f / ssum;
        for (int j = 0; j < 56; ++j) row[j] *= inv;
    }
    __syncthreads();

    // ============ Stage C3: out[c][i] = sum_j v[c][j]*attn[i][j]; x = gamma*out + x ============
    {
        float g = gamma[0];
        if (t < 224) {
            int c = t / 7, pi = t % 7;
            float acc[8] = {0,0,0,0,0,0,0,0};
            const float* vr = sm + V_OFF + c * 56;
            const float* ar = sm + ATT_OFF + pi * 8 * 57;
            for (int j = 0; j < 56; ++j) {
                float vv = vr[j];
                #pragma unroll
                for (int ii = 0; ii < 8; ++ii)
                    acc[ii] = fmaf(vv, ar[ii * 57 + j], acc[ii]);
            }
            float* xo = xbuf + c * 56 + pi * 8;
            #pragma unroll
            for (int ii = 0; ii < 8; ++ii) xo[ii] = fmaf(g, acc[ii], xo[ii]);
        }
    }
    __syncthreads();

    // ============ Stage D: LayerNorm over 32*7*8=1792, write padded xpadA ============
    float* xpadA = sm + R1_OFF;
    float* xpadB = sm + R2_OFF;
    {
        float s1 = 0.f, s2 = 0.f;
        #pragma unroll
        for (int k2 = 0; k2 < 7; ++k2) {
            float v = xbuf[t + k2 * 256];
            s1 += v; s2 = fmaf(v, v, s2);
        }
        #pragma unroll
        for (int off = 16; off; off >>= 1) {
            s1 += __shfl_xor_sync(0xffffffffu, s1, off);
            s2 += __shfl_xor_sync(0xffffffffu, s2, off);
        }
        if ((t & 31) == 0) { red[t >> 5] = s1; red[8 + (t >> 5)] = s2; }
        __syncthreads();
        if (t == 0) {
            float S1 = 0.f, S2 = 0.f;
            for (int w = 0; w < 8; ++w) { S1 += red[w]; S2 += red[8 + w]; }
            float mu = S1 * (1.f / 1792.f);
            float var = S2 * (1.f / 1792.f) - mu * mu;
            red[16] = mu;
            red[17] = rsqrtf(var + EPSV);
        }
        __syncthreads();
        float mu = red[16], inv = red[17];
        float vals[7];
        #pragma unroll
        for (int k2 = 0; k2 < 7; ++k2) {
            int idx = t + k2 * 256;
            vals[k2] = (xbuf[idx] - mu) * inv * ln_w[idx] + ln_b[idx];
        }
        __syncthreads();   // all xbuf reads done before zeroing xpadB over it
        for (int idx = t; idx < 3456; idx += 256) { xpadA[idx] = 0.f; xpadB[idx] = 0.f; }
        // stage w_res first half (input channels 0..15) while zeroing
        for (int idx = t; idx < 4608; idx += 256) {
            int o = idx / 144, r = idx - o * 144;
            ws[o * 145 + r] = w_res[o * 288 + r];
        }
        __syncthreads();
        #pragma unroll
        for (int k2 = 0; k2 < 7; ++k2) {
            int idx = t + k2 * 256;
            int c = idx / 56, s = idx - c * 56, p = s >> 3, q = s & 7;
            xpadA[c * 108 + (p + 1) * 12 + (q + 1)] = vals[k2];
        }
    }
    __syncthreads();

    // ============ Stage E: residual 3x3 conv 32->32 + BN + ReLU + residual -> xpadB ============
    {
        int o = 0, p = 0;
        bool act = (t < 224);
        if (act) { o = t / 7; p = t % 7; }
        float acc[8] = {0,0,0,0,0,0,0,0};
        if (act) conv3x3_row(acc, xpadA, ws + o * 145, 16, p);          // channels 0..15
        __syncthreads();
        for (int idx = t; idx < 4608; idx += 256) {                      // second half weights
            int oo = idx / 144, r = idx - oo * 144;
            ws[oo * 145 + r] = w_res[oo * 288 + 144 + r];
        }
        __syncthreads();
        if (act) {
            conv3x3_row(acc, xpadA + 16 * 108, ws + o * 145, 16, p);    // channels 16..31
            float sc = bnres_w[o] * rsqrtf(bnres_v[o] + EPSV);
            float bi = b_res[o] * sc + bnres_b[o] - bnres_m[o] * sc;
            float* dst = xpadB + o * 108 + (p + 1) * 12 + 1;
            const float* rsd = xpadA + o * 108 + (p + 1) * 12 + 1;
            #pragma unroll
            for (int q = 0; q < 8; ++q)
                dst[q] = fmaxf(fmaf(acc[q], sc, bi), 0.f) + rsd[q];
        }
    }
    __syncthreads();

    // ============ stage w1 (16x32x3x3) and w2 (1x16x3x3) ============
    for (int idx = t; idx < 4608; idx += 256) {
        int o = idx / 288, r = idx - o * 288;
        ws[o * 289 + r] = w1[idx];
    }
    for (int idx = t; idx < 144; idx += 256) ws[4624 + idx] = w2[idx];
    __syncthreads();

    // ============ Stage F: conv1 3x3 32->16 + BN + ReLU -> xpadA channels 0..15 ============
    if (t < 112) {
        int o = t / 7, p = t % 7;
        float acc[8] = {0,0,0,0,0,0,0,0};
        conv3x3_row(acc, xpadB, ws + o * 289, 32, p);
        float sc = bn1_w[o] * rsqrtf(bn1_v[o] + EPSV);
        float bi = b1[o] * sc + bn1_b[o] - bn1_m[o] * sc;
        float* dst = xpadA + o * 108 + (p + 1) * 12 + 1;
        #pragma unroll
        for (int q = 0; q < 8; ++q) dst[q] = fmaxf(fmaf(acc[q], sc, bi), 0.f);
    }
    __syncthreads();

    // ============ Stage G: conv2 3x3 16->1 -> out ============
    if (t < 56) {
        int p = t >> 3, q = t & 7;
        float acc2 = b2[0];
        const float* wk = ws + 4624;
        for (int i = 0; i < 16; ++i) {
            const float* xc = xpadA + i * 108 + p * 12 + q;
            const float* w = wk + i * 9;
            acc2 = fmaf(w[0], xc[0],  acc2);
            acc2 = fmaf(w[1], xc[1],  acc2);
            acc2 = fmaf(w[2], xc[2],  acc2);
            acc2 = fmaf(w[3], xc[12], acc2);
            acc2 = fmaf(w[4], xc[13], acc2);
            acc2 = fmaf(w[5], xc[14], acc2);
            acc2 = fmaf(w[6], xc[24], acc2);
            acc2 = fmaf(w[7], xc[25], acc2);
            acc2 = fmaf(w[8], xc[26], acc2);
        }
        out[(size_t)b * 56 + t] = acc2;
    }
}

extern "C" void kernel_launch(void* const* d_in, const int* in_sizes, int n_in,
                              void* d_out, int out_size) {
    const float* mg      = (const float*)d_in[0];
    const float* w_cr    = (const float*)d_in[1];
    const float* b_cr    = (const float*)d_in[2];
    const float* bnr_w   = (const float*)d_in[3];
    const float* bnr_b   = (const float*)d_in[4];
    const float* bnr_m   = (const float*)d_in[5];
    const float* bnr_v   = (const float*)d_in[6];
    const float* q_w     = (const float*)d_in[7];
    const float* q_b     = (const float*)d_in[8];
    const float* k_w     = (const float*)d_in[9];
    const float* k_b     = (const float*)d_in[10];
    const float* v_w     = (const float*)d_in[11];
    const float* v_b     = (const float*)d_in[12];
    const float* gamma   = (const float*)d_in[13];
    const float* ln_w    = (const float*)d_in[14];
    const float* ln_b    = (const float*)d_in[15];
    const float* w_res   = (const float*)d_in[16];
    const float* b_res   = (const float*)d_in[17];
    const float* bnres_w = (const float*)d_in[18];
    const float* bnres_b = (const float*)d_in[19];
    const float* bnres_m = (const float*)d_in[20];
    const float* bnres_v = (const float*)d_in[21];
    const float* w1      = (const float*)d_in[22];
    const float* b1      = (const float*)d_in[23];
    const float* bn1_w   = (const float*)d_in[24];
    const float* bn1_b   = (const float*)d_in[25];
    const float* bn1_m   = (const float*)d_in[26];
    const float* bn1_v   = (const float*)d_in[27];
    const float* w2      = (const float*)d_in[28];
    const float* b2      = (const float*)d_in[29];

    int B = in_sizes[0] / 32768;   // 128*16*16 per sample
    size_t smem_bytes = SMEM_FLOATS * sizeof(float);
    cudaFuncSetAttribute(occ_fused_kernel,
                         cudaFuncAttributeMaxDynamicSharedMemorySize, (int)smem_bytes);
    occ_fused_kernel<<<B, 256, smem_bytes>>>(
        mg, w_cr, b_cr, bnr_w, bnr_b, bnr_m, bnr_v,
        q_w, q_b, k_w, k_b, v_w, v_b, gamma, ln_w, ln_b,
        w_res, b_res, bnres_w, bnres_b, bnres_m, bnres_v,
        w1, b1, bn1_w, bn1_b, bn1_m, bn1_v, w2, b2,
        (float*)d_out);
}